// round 5
// baseline (speedup 1.0000x reference)
#include <cuda_runtime.h>
#include <math.h>

#define BB   8192
#define INF  512
#define OUTF 1024
#define KWID 1535   // weight row length (IN_F + OUT_F - 1)
#define CB   64
#define NBLK (OUTF / CB)

// Column-major fp32 buffers: [col * BB + row]
__device__ float g_XW[(size_t)BB * OUTF];  // x @ Wx^T + bias (ref chain order)
__device__ float g_D [(size_t)BB * OUTF];  // prefix dot chain  sum_{j<base} out_j*Wo[col,j]

// ---------------------------------------------------------------------------
// XLA-faithful fp32 logistic: 0.5*fast_tanh(0.5*x) + 0.5, with EmitFastTanh's
// rational approximation. All mul/add UNFUSED (XLA emits raw FMul/FAdd with
// no fast-math flags => LLVM does not contract).
// ---------------------------------------------------------------------------
__device__ __forceinline__ float xla_fast_tanh(float x)
{
    float ax = fabsf(x);
    float xc = fminf(fmaxf(x, -7.90531110763549805f), 7.90531110763549805f);
    float x2 = __fmul_rn(xc, xc);
    float np = __fadd_rn(__fmul_rn(x2, -2.76076847742355e-16f), 2.00018790482477e-13f);
    np = __fadd_rn(__fmul_rn(x2, np), -8.60467152213735e-11f);
    np = __fadd_rn(__fmul_rn(x2, np),  5.12229709037114e-08f);
    np = __fadd_rn(__fmul_rn(x2, np),  1.48572235717979e-05f);
    np = __fadd_rn(__fmul_rn(x2, np),  6.37261928875436e-04f);
    np = __fadd_rn(__fmul_rn(x2, np),  4.89352455891786e-03f);
    np = __fmul_rn(xc, np);
    float dq = __fadd_rn(__fmul_rn(x2, 1.19825839466702e-06f), 1.18534705686654e-04f);
    dq = __fadd_rn(__fmul_rn(x2, dq), 2.26843463243900e-03f);
    dq = __fadd_rn(__fmul_rn(x2, dq), 4.89352518554385e-03f);
    float r = __fdiv_rn(np, dq);
    return (ax < 0.0004f) ? x : r;
}

__device__ __forceinline__ float xla_logistic_f32(float x)
{
    float t = xla_fast_tanh(__fmul_rn(0.5f, x));
    return __fadd_rn(__fmul_rn(0.5f, t), 0.5f);
}

// ---------------------------------------------------------------------------
// GEMM: dst[col][m] = chain_{k=0..K-1} fma(A[m][k], W[col*KWID+koff+k]) (+bias)
// Per output element: ONE fp32 accumulator, strict ascending-k FMA chain --
// bit-matches Eigen gebp's per-element accumulation (single kc panel).
// 64x64 tile, BK=16, 256 threads, 4x4 microtile. Writes column-major.
// mode 0: + bias (separate fp32 add, like XLA's fused bias) -> g_XW
// mode 1: raw chain -> g_D
// ---------------------------------------------------------------------------
__global__ void __launch_bounds__(256)
gemm_kernel(const float* __restrict__ A, const float* __restrict__ W,
            const float* __restrict__ bias, float* __restrict__ dst,
            int K, int nbase0, int koff, int lda, int mode)
{
    __shared__ float As[16][68];
    __shared__ float Bs[16][68];
    const int tid   = threadIdx.x;
    const int m0    = blockIdx.x * 64;
    const int nbase = nbase0 + blockIdx.y * 64;
    const int tx = tid & 15;
    const int ty = tid >> 4;
    const int am = tid >> 2;          // 0..63 row of A tile
    const int ak = (tid & 3) << 2;    // 0,4,8,12
    const int bk = tid & 15;
    const int bn = tid >> 4;

    float acc[4][4];
#pragma unroll
    for (int i = 0; i < 4; ++i)
#pragma unroll
        for (int j = 0; j < 4; ++j) acc[i][j] = 0.0f;

    const float* Arow  = A + (size_t)(m0 + am) * lda + ak;
    const float* Wbase = W + (size_t)koff;

    for (int k0 = 0; k0 < K; k0 += 16) {
        float4 av = *reinterpret_cast<const float4*>(Arow + k0);
        As[ak + 0][am] = av.x;
        As[ak + 1][am] = av.y;
        As[ak + 2][am] = av.z;
        As[ak + 3][am] = av.w;
#pragma unroll
        for (int q = 0; q < 4; ++q) {
            int n = bn + q * 16;
            Bs[bk][n] = Wbase[(size_t)(nbase + n) * KWID + k0 + bk];
        }
        __syncthreads();
#pragma unroll
        for (int kk = 0; kk < 16; ++kk) {   // strict ascending k, single acc
            float4 a4 = *reinterpret_cast<const float4*>(&As[kk][ty << 2]);
            float4 b4 = *reinterpret_cast<const float4*>(&Bs[kk][tx << 2]);
            float a[4] = {a4.x, a4.y, a4.z, a4.w};
            float b[4] = {b4.x, b4.y, b4.z, b4.w};
#pragma unroll
            for (int i = 0; i < 4; ++i)
#pragma unroll
                for (int j = 0; j < 4; ++j)
                    acc[i][j] = fmaf(a[i], b[j], acc[i][j]);
        }
        __syncthreads();
    }

#pragma unroll
    for (int j = 0; j < 4; ++j) {
        int col = nbase + (tx << 2) + j;
        float* d = dst + (size_t)col * BB + m0 + (ty << 2);
        float4 v;
        if (mode == 0) {
            float bv = bias[col];
            v.x = __fadd_rn(acc[0][j], bv);
            v.y = __fadd_rn(acc[1][j], bv);
            v.z = __fadd_rn(acc[2][j], bv);
            v.w = __fadd_rn(acc[3][j], bv);
        } else {
            v.x = acc[0][j]; v.y = acc[1][j]; v.z = acc[2][j]; v.w = acc[3][j];
        }
        *reinterpret_cast<float4*>(d) = v;
    }
}

// ---------------------------------------------------------------------------
// Sequential sweep over one 64-column block. One thread per batch row.
// accf[i] CONTINUES the fp32 j-ordered chain started by the block GEMM
// (init from g_D; zero for block 0). logit = fp32_add(xw_i, chain) -- exactly
// the reference's  logit = xw_i + (out @ wo_row).  Sampling via the XLA
// logistic on every element; strict fp32 compare u < p.
// ---------------------------------------------------------------------------
__global__ void __launch_bounds__(64)
seq_kernel(int base, const float* __restrict__ W, const float* __restrict__ U,
           float* __restrict__ out, float* __restrict__ Lout)
{
    __shared__ float tri[CB][CB + 1];      // tri[i][j] = Wo[base+j][base+i]
    __shared__ float uv[CB][CB + 1];       // u, then reused to stash logits
    __shared__ unsigned char ss[CB][CB + 4];
    const int tid = threadIdx.x;
    const int r0  = blockIdx.x * CB;

    {   // coalesced in tid; clamp the single OOB element (never consumed)
        int ci = INF + base + tid;
        if (ci > KWID - 1) ci = KWID - 1;
#pragma unroll 1
        for (int j = 0; j < CB; ++j)
            tri[tid][j] = W[(size_t)(base + j) * KWID + ci];
    }
#pragma unroll 1
    for (int rr = 0; rr < CB; ++rr)
        uv[rr][tid] = U[(size_t)(r0 + rr) * OUTF + base + tid];
    __syncthreads();

    const int r = r0 + tid;
    const float* xwc = g_XW + (size_t)base * BB + r;   // step i: xwc[i*BB]
    const float* dc  = g_D  + (size_t)base * BB + r;

    float accf[CB];
    if (base == 0) {
#pragma unroll
        for (int i = 0; i < CB; ++i) accf[i] = 0.0f;
    } else {
#pragma unroll
        for (int i = 0; i < CB; ++i) accf[i] = dc[(size_t)i * BB];
    }

    float pre[16];
#pragma unroll
    for (int t = 0; t < 16; ++t) pre[t] = xwc[(size_t)t * BB];

#pragma unroll
    for (int i = 0; i < CB; ++i) {
        float xwv = pre[i & 15];
        if (i + 16 < CB) pre[i & 15] = xwc[(size_t)(i + 16) * BB];

        float logit_f = __fadd_rn(xwv, accf[i]);
        float uu = uv[tid][i];
        float p  = xla_logistic_f32(logit_f);
        float s  = (uu < p) ? 1.0f : 0.0f;

        ss[tid][i] = (unsigned char)(uu < p);
        uv[tid][i] = logit_f;              // stash logit for coalesced out
#pragma unroll
        for (int j = i + 1; j < CB; ++j)   // continue each target's chain
            accf[j] = fmaf(s, tri[i][j], accf[j]);
    }
    __syncthreads();

    // coalesced write-out (lane = column)
#pragma unroll 1
    for (int rr = 0; rr < CB; ++rr) {
        Lout[(size_t)(r0 + rr) * OUTF + base + tid] = uv[rr][tid];
        out [(size_t)(r0 + rr) * OUTF + base + tid] = (float)ss[rr][tid];
    }
}

// ---------------------------------------------------------------------------
// Launch: xw GEMM, then 16 x (block GEMM over the full prefix j<base in
// strict j order + sequential sweep). d_out: [out][logits], both B*OUT_F fp32.
// ---------------------------------------------------------------------------
extern "C" void kernel_launch(void* const* d_in, const int* in_sizes, int n_in,
                              void* d_out, int out_size)
{
    const float* x    = (const float*)d_in[0];
    const float* w    = (const float*)d_in[1];
    const float* bias = (const float*)d_in[2];
    const float* u    = (const float*)d_in[3];
    float* out  = (float*)d_out;
    float* Lout = out + (size_t)BB * OUTF;

    float* xw_ptr;  cudaGetSymbolAddress((void**)&xw_ptr, g_XW);
    float* d_ptr;   cudaGetSymbolAddress((void**)&d_ptr,  g_D);

    // g_XW = x @ Wx^T + bias (per-element strict k-chain, then one bias add)
    gemm_kernel<<<dim3(BB / 64, OUTF / 64), 256>>>(x, w, bias, xw_ptr,
                                                   INF, 0, 0, INF, 0);
    for (int k = 0; k < NBLK; ++k) {
        int base = k * CB;
        if (k > 0)
            // g_D[:, base:base+64] = chain_{j=0..base-1} out_j * Wo[col, j]
            gemm_kernel<<<dim3(BB / 64, 1), 256>>>(out, w, bias, d_ptr,
                                                   base, base, INF, OUTF, 1);
        seq_kernel<<<BB / CB, CB>>>(base, w, u, out, Lout);
    }
}

// round 6
// speedup vs baseline: 1.7230x; 1.7230x over previous
#include <cuda_runtime.h>
#include <math.h>

#define BB   8192
#define INF  512
#define OUTF 1024
#define KWID 1535   // weight row length (IN_F + OUT_F - 1)
#define CB   64
#define NBLK (OUTF / CB)
#define TT   4      // slot-threads per row
#define SL   16     // slots (columns) per thread  (CB/TT)

// Column-major fp32 buffers: [col * BB + row]
__device__ float g_XW[(size_t)BB * OUTF];  // x @ Wx^T + bias (ref chain order)
__device__ float g_D [(size_t)BB * OUTF];  // prefix dot chain sum_{j<base} out_j*Wo[col,j]

// ---------------------------------------------------------------------------
// XLA-faithful fp32 logistic: 0.5*fast_tanh(0.5*x) + 0.5 (EmitFastTanh
// rational approx). All mul/add UNFUSED, matching XLA's raw FMul/FAdd.
// ---------------------------------------------------------------------------
__device__ __forceinline__ float xla_fast_tanh(float x)
{
    float ax = fabsf(x);
    float xc = fminf(fmaxf(x, -7.90531110763549805f), 7.90531110763549805f);
    float x2 = __fmul_rn(xc, xc);
    float np = __fadd_rn(__fmul_rn(x2, -2.76076847742355e-16f), 2.00018790482477e-13f);
    np = __fadd_rn(__fmul_rn(x2, np), -8.60467152213735e-11f);
    np = __fadd_rn(__fmul_rn(x2, np),  5.12229709037114e-08f);
    np = __fadd_rn(__fmul_rn(x2, np),  1.48572235717979e-05f);
    np = __fadd_rn(__fmul_rn(x2, np),  6.37261928875436e-04f);
    np = __fadd_rn(__fmul_rn(x2, np),  4.89352455891786e-03f);
    np = __fmul_rn(xc, np);
    float dq = __fadd_rn(__fmul_rn(x2, 1.19825839466702e-06f), 1.18534705686654e-04f);
    dq = __fadd_rn(__fmul_rn(x2, dq), 2.26843463243900e-03f);
    dq = __fadd_rn(__fmul_rn(x2, dq), 4.89352518554385e-03f);
    float r = __fdiv_rn(np, dq);
    return (ax < 0.0004f) ? x : r;
}

__device__ __forceinline__ float xla_logistic_f32(float x)
{
    float t = xla_fast_tanh(__fmul_rn(0.5f, x));
    return __fadd_rn(__fmul_rn(0.5f, t), 0.5f);
}

// ---------------------------------------------------------------------------
// GEMM: dst[col][m] = chain_{k} fma(A[m][k], W[col*KWID+koff+k]) (+bias)
// Per output element: ONE fp32 accumulator, strict ascending-k FMA chain
// (bit-matches Eigen gebp). 64x64 tile, BK=16, 256 threads, 4x4 microtile.
// mode 0: + bias -> g_XW.   mode 1: raw chain -> g_D.   (UNCHANGED from R5)
// ---------------------------------------------------------------------------
__global__ void __launch_bounds__(256)
gemm_kernel(const float* __restrict__ A, const float* __restrict__ W,
            const float* __restrict__ bias, float* __restrict__ dst,
            int K, int nbase0, int koff, int lda, int mode)
{
    __shared__ float As[16][68];
    __shared__ float Bs[16][68];
    const int tid   = threadIdx.x;
    const int m0    = blockIdx.x * 64;
    const int nbase = nbase0 + blockIdx.y * 64;
    const int tx = tid & 15;
    const int ty = tid >> 4;
    const int am = tid >> 2;
    const int ak = (tid & 3) << 2;
    const int bk = tid & 15;
    const int bn = tid >> 4;

    float acc[4][4];
#pragma unroll
    for (int i = 0; i < 4; ++i)
#pragma unroll
        for (int j = 0; j < 4; ++j) acc[i][j] = 0.0f;

    const float* Arow  = A + (size_t)(m0 + am) * lda + ak;
    const float* Wbase = W + (size_t)koff;

    for (int k0 = 0; k0 < K; k0 += 16) {
        float4 av = *reinterpret_cast<const float4*>(Arow + k0);
        As[ak + 0][am] = av.x;
        As[ak + 1][am] = av.y;
        As[ak + 2][am] = av.z;
        As[ak + 3][am] = av.w;
#pragma unroll
        for (int q = 0; q < 4; ++q) {
            int n = bn + q * 16;
            Bs[bk][n] = Wbase[(size_t)(nbase + n) * KWID + k0 + bk];
        }
        __syncthreads();
#pragma unroll
        for (int kk = 0; kk < 16; ++kk) {
            float4 a4 = *reinterpret_cast<const float4*>(&As[kk][ty << 2]);
            float4 b4 = *reinterpret_cast<const float4*>(&Bs[kk][tx << 2]);
            float a[4] = {a4.x, a4.y, a4.z, a4.w};
            float b[4] = {b4.x, b4.y, b4.z, b4.w};
#pragma unroll
            for (int i = 0; i < 4; ++i)
#pragma unroll
                for (int j = 0; j < 4; ++j)
                    acc[i][j] = fmaf(a[i], b[j], acc[i][j]);
        }
        __syncthreads();
    }

#pragma unroll
    for (int j = 0; j < 4; ++j) {
        int col = nbase + (tx << 2) + j;
        float* d = dst + (size_t)col * BB + m0 + (ty << 2);
        float4 v;
        if (mode == 0) {
            float bv = bias[col];
            v.x = __fadd_rn(acc[0][j], bv);
            v.y = __fadd_rn(acc[1][j], bv);
            v.z = __fadd_rn(acc[2][j], bv);
            v.w = __fadd_rn(acc[3][j], bv);
        } else {
            v.x = acc[0][j]; v.y = acc[1][j]; v.z = acc[2][j]; v.w = acc[3][j];
        }
        *reinterpret_cast<float4*>(d) = v;
    }
}

// ---------------------------------------------------------------------------
// Slot-split sequential sweep: 256 threads = 64 rows x 4 slot-threads.
// Lane layout (within warp): lane = row*4 + t; thread t owns columns
// c = t*16 + m (m = 0..15). Column c's chain finalizes at global step i = c,
// where its OWNER thread computes logit = fadd(xw_c, accf[m]) and the sample;
// the sample is broadcast intra-warp via shfl. tri[i][j] is ZERO for j <= i,
// so every lane can unconditionally FMA all 16 of its slots each step:
// fma(s, 0, acc) == acc exactly => per-slot chain order is bit-identical to
// round 5 (strict ascending i, real terms only).
// Sub-round structure: runtime g = 0..3 (owner t == g), inner 16 steps
// unrolled => accf stays register-indexed, SASS body ~13 KB (fits I$).
// ---------------------------------------------------------------------------
__global__ void __launch_bounds__(256)
seq_kernel(int base, const float* __restrict__ W, const float* __restrict__ U,
           float* __restrict__ out, float* __restrict__ Lout)
{
    __shared__ __align__(16) float tri[CB][CB + 4]; // tri[i][j], 0 for j<=i
    __shared__ __align__(16) float stg[CB][CB + 4]; // staging: logits, then samples
    const int tid  = threadIdx.x;       // 256
    const int r0   = blockIdx.x * CB;
    const int rl   = tid >> 2;          // row 0..63
    const int t    = tid & 3;           // slot group 0..3
    const int r    = r0 + rl;
    const int lane = tid & 31;

    // Fill zero-padded triangle: tri[i][j] = (j > i) ? Wo[base+j][base+i] : 0.
    // idx: i fastest => W reads coalesced (i is the contiguous k index).
#pragma unroll 1
    for (int idx = tid; idx < CB * CB; idx += 256) {
        int i = idx & (CB - 1);
        int j = idx >> 6;
        float v = 0.0f;
        if (j > i) v = W[(size_t)(base + j) * KWID + INF + base + i];
        tri[i][j] = v;
    }
    __syncthreads();

    // Per-lane loads: u, xw, chain-init for its 16 columns (c = t*16 + m).
    float ureg[SL], xwreg[SL], accf[SL], logits[SL];
    {
        const float* Urow = U + (size_t)r * OUTF + base + (t << 4);
#pragma unroll
        for (int m = 0; m < SL; m += 4) {
            float4 v = *reinterpret_cast<const float4*>(Urow + m);
            ureg[m] = v.x; ureg[m+1] = v.y; ureg[m+2] = v.z; ureg[m+3] = v.w;
        }
    }
#pragma unroll
    for (int m = 0; m < SL; ++m)
        xwreg[m] = g_XW[(size_t)(base + (t << 4) + m) * BB + r];
    if (base == 0) {
#pragma unroll
        for (int m = 0; m < SL; ++m) accf[m] = 0.0f;
    } else {
#pragma unroll
        for (int m = 0; m < SL; ++m)
            accf[m] = g_D[(size_t)(base + (t << 4) + m) * BB + r];
    }

    unsigned smask = 0u;
    const float* tbase = &tri[0][0] + (t << 4);

#pragma unroll 1
    for (int g = 0; g < TT; ++g) {
        const int src = (lane & ~3) | g;       // owner lane for this sub-round
#pragma unroll
        for (int m = 0; m < SL; ++m) {
            const int i = (g << 4) + m;        // global step
            // candidate logit/sample on every lane (only owner's is real)
            float cand = __fadd_rn(xwreg[m], accf[m]);
            float p    = xla_logistic_f32(cand);
            float sc   = (ureg[m] < p) ? 1.0f : 0.0f;
            float s    = __shfl_sync(0xffffffffu, sc, src);
            if (t == g) {                      // owner keeps its results
                logits[m] = cand;
                smask |= (sc != 0.0f ? 1u : 0u) << m;
            }
            // unconditional rank-1 update of this lane's 16 slots
            const float* trow = tbase + i * (CB + 4);
#pragma unroll
            for (int mm = 0; mm < SL; mm += 4) {
                float4 tv = *reinterpret_cast<const float4*>(trow + mm);
                accf[mm + 0] = fmaf(s, tv.x, accf[mm + 0]);
                accf[mm + 1] = fmaf(s, tv.y, accf[mm + 1]);
                accf[mm + 2] = fmaf(s, tv.z, accf[mm + 2]);
                accf[mm + 3] = fmaf(s, tv.w, accf[mm + 3]);
            }
        }
    }

    // Stage logits, write coalesced.
#pragma unroll
    for (int m = 0; m < SL; m += 4) {
        float4 v; v.x = logits[m]; v.y = logits[m+1]; v.z = logits[m+2]; v.w = logits[m+3];
        *reinterpret_cast<float4*>(&stg[rl][(t << 4) + m]) = v;
    }
    __syncthreads();
#pragma unroll 1
    for (int idx = tid; idx < CB * CB; idx += 256) {
        int rr = idx >> 6, c = idx & (CB - 1);
        Lout[(size_t)(r0 + rr) * OUTF + base + c] = stg[rr][c];
    }
    __syncthreads();
    // Stage samples, write coalesced.
#pragma unroll
    for (int m = 0; m < SL; m += 4) {
        float4 v;
        v.x = (float)((smask >> (m + 0)) & 1u);
        v.y = (float)((smask >> (m + 1)) & 1u);
        v.z = (float)((smask >> (m + 2)) & 1u);
        v.w = (float)((smask >> (m + 3)) & 1u);
        *reinterpret_cast<float4*>(&stg[rl][(t << 4) + m]) = v;
    }
    __syncthreads();
#pragma unroll 1
    for (int idx = tid; idx < CB * CB; idx += 256) {
        int rr = idx >> 6, c = idx & (CB - 1);
        out[(size_t)(r0 + rr) * OUTF + base + c] = stg[rr][c];
    }
}

// ---------------------------------------------------------------------------
// Launch: xw GEMM, then 16 x (prefix block GEMM + sweep).
// d_out: [out][logits], both B*OUT_F fp32.
// ---------------------------------------------------------------------------
extern "C" void kernel_launch(void* const* d_in, const int* in_sizes, int n_in,
                              void* d_out, int out_size)
{
    const float* x    = (const float*)d_in[0];
    const float* w    = (const float*)d_in[1];
    const float* bias = (const float*)d_in[2];
    const float* u    = (const float*)d_in[3];
    float* out  = (float*)d_out;
    float* Lout = out + (size_t)BB * OUTF;

    float* xw_ptr;  cudaGetSymbolAddress((void**)&xw_ptr, g_XW);
    float* d_ptr;   cudaGetSymbolAddress((void**)&d_ptr,  g_D);

    gemm_kernel<<<dim3(BB / 64, OUTF / 64), 256>>>(x, w, bias, xw_ptr,
                                                   INF, 0, 0, INF, 0);
    for (int k = 0; k < NBLK; ++k) {
        int base = k * CB;
        if (k > 0)
            gemm_kernel<<<dim3(BB / 64, 1), 256>>>(out, w, bias, d_ptr,
                                                   base, base, INF, OUTF, 1);
        seq_kernel<<<BB / CB, 256>>>(base, w, u, out, Lout);
    }
}